// round 1
// baseline (speedup 1.0000x reference)
#include <cuda_runtime.h>
#include <math.h>

#define NB 4
#define NA 262144
#define PRE 4000
#define POST 1000
#define SORTN 4096
#define NT 1024

static __device__ const float NMS_TH = 0.3f;
static __device__ const float AUG = 0.2f;

// ---- shared memory layout (bytes) ----
static const int OFF_KEYS = 0;                         // 4096 * u64      = 32768
static const int OFF_GEO  = OFF_KEYS + SORTN * 8;      // 7 * 4096 float  = 114688
static const int OFF_SIDX = OFF_GEO + 7 * SORTN * 4;   // 4096 * int      = 16384
static const int OFF_ORD  = OFF_SIDX + SORTN * 4;      // 1024 * int      = 4096
static const int OFF_HIST = OFF_ORD + 1024 * 4;        // 8*256 * uint    = 8192
static const int OFF_KEEP = OFF_HIST + 8 * 256 * 4;    // 4096 bytes
static const int OFF_CNT  = OFF_KEEP + SORTN;          // counters
static const int SMEM_BYTES = OFF_CNT + 64;            // = 180352-ish (180288+pad)

__device__ __forceinline__ unsigned mapf(float v) {
    unsigned u = __float_as_uint(v);
    return (u & 0x80000000u) ? ~u : (u | 0x80000000u);
}

__device__ __forceinline__ void decode_box(const float* __restrict__ rg,
                                           const float* __restrict__ an,
                                           float* bx) {
    float xa = an[0], ya = an[1], za = an[2];
    float wa = an[3], la = an[4], ha = an[5], ra = an[6];
    float dx = rg[0], dy = rg[1], dz = rg[2];
    float dw = rg[3], dl = rg[4], dh = rg[5], dr = rg[6];
    float diag = sqrtf(wa * wa + la * la);
    bx[0] = dx * diag + xa;
    bx[1] = dy * diag + ya;
    bx[2] = dz * ha + za;
    bx[3] = expf(dw) * wa;
    bx[4] = expf(dl) * la;
    bx[5] = expf(dh) * ha;
    bx[6] = dr + ra;
}

__global__ void __launch_bounds__(NT) rpn_post_kernel(
    const float* __restrict__ obj,
    const float* __restrict__ reg,
    const float* __restrict__ anc,
    float* __restrict__ out)
{
    extern __shared__ unsigned char smem[];
    unsigned long long* keys = (unsigned long long*)(smem + OFF_KEYS);
    float* lox = (float*)(smem + OFF_GEO);
    float* loy = lox + SORTN;
    float* loz = loy + SORTN;
    float* hix = loz + SORTN;
    float* hiy = hix + SORTN;
    float* hiz = hiy + SORTN;
    float* vol = hiz + SORTN;
    int* sidx      = (int*)(smem + OFF_SIDX);
    int* order     = (int*)(smem + OFF_ORD);
    unsigned* hist = (unsigned*)(smem + OFF_HIST);
    unsigned char* keep = (unsigned char*)(smem + OFF_KEEP);
    int* cnts      = (int*)(smem + OFF_CNT);
    // cnts[0]=compact count, cnts[1]=kept count, cnts[2]=bucket, cnts[3]=need

    const int b = blockIdx.x;
    const int tid = threadIdx.x;
    const float* objb = obj + (size_t)b * NA;
    const float4* o4 = (const float4*)objb;
    const int rep = (tid >> 5) & 7;

    // ================= 1) exact radix select of 4000th-largest key =================
    unsigned prefix = 0;
    int need = PRE;
    for (int pass = 0; pass < 4; ++pass) {
        const int shift = 24 - 8 * pass;
        for (int i = tid; i < 8 * 256; i += NT) hist[i] = 0;
        __syncthreads();
        const unsigned pmask = (pass == 0) ? 0u : (0xFFFFFFFFu << (shift + 8));
        for (int i = tid; i < NA / 4; i += NT) {
            float4 v = o4[i];
            unsigned u0 = mapf(v.x), u1 = mapf(v.y), u2 = mapf(v.z), u3 = mapf(v.w);
            if ((u0 & pmask) == prefix) atomicAdd(&hist[rep * 256 + ((u0 >> shift) & 255)], 1u);
            if ((u1 & pmask) == prefix) atomicAdd(&hist[rep * 256 + ((u1 >> shift) & 255)], 1u);
            if ((u2 & pmask) == prefix) atomicAdd(&hist[rep * 256 + ((u2 >> shift) & 255)], 1u);
            if ((u3 & pmask) == prefix) atomicAdd(&hist[rep * 256 + ((u3 >> shift) & 255)], 1u);
        }
        __syncthreads();
        unsigned s = 0;
        if (tid < 256) {
            #pragma unroll
            for (int r = 0; r < 8; ++r) s += hist[r * 256 + tid];
        }
        __syncthreads();
        if (tid < 256) hist[tid] = s;
        __syncthreads();
        if (tid == 0) {
            int cum = 0;
            int bsel = 0, nn = need;
            for (int bb = 255; bb >= 0; --bb) {
                cum += (int)hist[bb];
                if (cum >= need) {
                    bsel = bb;
                    nn = need - (cum - (int)hist[bb]);
                    break;
                }
            }
            cnts[2] = bsel;
            cnts[3] = nn;
        }
        __syncthreads();
        prefix |= ((unsigned)cnts[2]) << shift;
        need = cnts[3];
        __syncthreads();
    }
    const unsigned T = prefix;  // exact mapped value of the 4000th-largest score

    // ================= 2) compact all candidates >= T into SMEM =================
    if (tid == 0) cnts[0] = 0;
    __syncthreads();
    for (int i = tid; i < NA / 4; i += NT) {
        float4 v = o4[i];
        unsigned uu0 = mapf(v.x), uu1 = mapf(v.y), uu2 = mapf(v.z), uu3 = mapf(v.w);
        if (uu0 >= T) { int p = atomicAdd(&cnts[0], 1); if (p < SORTN) keys[p] = ((unsigned long long)uu0 << 32) | (unsigned)(~(4 * i + 0)); }
        if (uu1 >= T) { int p = atomicAdd(&cnts[0], 1); if (p < SORTN) keys[p] = ((unsigned long long)uu1 << 32) | (unsigned)(~(4 * i + 1)); }
        if (uu2 >= T) { int p = atomicAdd(&cnts[0], 1); if (p < SORTN) keys[p] = ((unsigned long long)uu2 << 32) | (unsigned)(~(4 * i + 2)); }
        if (uu3 >= T) { int p = atomicAdd(&cnts[0], 1); if (p < SORTN) keys[p] = ((unsigned long long)uu3 << 32) | (unsigned)(~(4 * i + 3)); }
    }
    __syncthreads();
    int cc = cnts[0];
    if (cc > SORTN) cc = SORTN;
    for (int i = cc + tid; i < SORTN; i += NT) keys[i] = 0ull;
    __syncthreads();

    // ================= 3) bitonic sort descending (ties -> lower index first) =================
    for (int k = 2; k <= SORTN; k <<= 1) {
        for (int j = k >> 1; j > 0; j >>= 1) {
            for (int t = tid; t < SORTN; t += NT) {
                int ixj = t ^ j;
                if (ixj > t) {
                    unsigned long long a = keys[t];
                    unsigned long long c2 = keys[ixj];
                    bool up = ((t & k) == 0);  // up segment => descending
                    if (up ? (a < c2) : (a > c2)) {
                        keys[t] = c2;
                        keys[ixj] = a;
                    }
                }
            }
            __syncthreads();
        }
    }

    // ================= 4) decode top-4000 boxes, build augmented AABBs in SMEM =================
    for (int r = tid; r < PRE; r += NT) {
        unsigned long long kk = keys[r];
        int idx = (int)(~(unsigned)(kk & 0xFFFFFFFFull));
        sidx[r] = idx;
        const float* rg = reg + ((size_t)b * NA + idx) * 7;
        const float* an = anc + ((size_t)b * NA + idx) * 7;
        float bx[7];
        decode_box(rg, an, bx);
        float sx = fmaxf(bx[3], AUG);
        float sy = fmaxf(bx[4], AUG);
        float sz = fmaxf(bx[5], AUG);
        lox[r] = bx[0] - sx * 0.5f;
        loy[r] = bx[1] - sy * 0.5f;
        loz[r] = bx[2];
        hix[r] = bx[0] + sx * 0.5f;
        hiy[r] = bx[1] + sy * 0.5f;
        hiz[r] = bx[2] + sz;
        vol[r] = sx * sy * sz;
        keep[r] = 1;
    }
    if (tid == 0) cnts[1] = 0;
    __syncthreads();

    // ================= 5) sequential greedy NMS, early stop at 1000 kept =================
    for (int i = 0; i < PRE; ++i) {
        if (cnts[1] >= POST) break;   // uniform across block (read post-barrier)
        if (keep[i]) {
            if (tid == 0) {
                int kc = cnts[1];
                order[kc] = i;
                cnts[1] = kc + 1;
            }
            float blx = lox[i], bly = loy[i], blz = loz[i];
            float bhx = hix[i], bhy = hiy[i], bhz = hiz[i];
            float bv = vol[i];
            for (int j = i + 1 + tid; j < PRE; j += NT) {
                if (!keep[j]) continue;
                float dxx = fminf(bhx, hix[j]) - fmaxf(blx, lox[j]);
                if (dxx <= 0.f) continue;
                float dyy = fminf(bhy, hiy[j]) - fmaxf(bly, loy[j]);
                if (dyy <= 0.f) continue;
                float dzz = fminf(bhz, hiz[j]) - fmaxf(blz, loz[j]);
                if (dzz <= 0.f) continue;
                float inter = dxx * dyy * dzz;
                float uni = bv + vol[j] - inter;
                float iou = inter / fmaxf(uni, 1e-8f);
                if (iou > NMS_TH) keep[j] = 0;
            }
        }
        __syncthreads();
    }
    __syncthreads();

    // ================= 6) write output: first min(kept,1000) rows, zero the rest =================
    int nk = cnts[1];
    if (nk > POST) nk = POST;
    float* outb = out + (size_t)b * POST * 8;
    for (int r = tid; r < POST; r += NT) {
        float row[8];
        if (r < nk) {
            int rr = order[r];
            int idx = sidx[rr];
            const float* rg = reg + ((size_t)b * NA + idx) * 7;
            const float* an = anc + ((size_t)b * NA + idx) * 7;
            decode_box(rg, an, row);
            float lg = objb[idx];
            row[7] = 1.0f / (1.0f + expf(-lg));
        } else {
            #pragma unroll
            for (int c = 0; c < 8; ++c) row[c] = 0.f;
        }
        #pragma unroll
        for (int c = 0; c < 8; ++c) outb[r * 8 + c] = row[c];
    }
}

extern "C" void kernel_launch(void* const* d_in, const int* in_sizes, int n_in,
                              void* d_out, int out_size) {
    const float* obj = (const float*)d_in[0];          // (B*A,)    objectness logits
    const float* reg = (const float*)d_in[1];          // (B*A, 7)  box_regression
    const float* anc = (const float*)d_in[2];          // (B*A, 7)  anchors
    float* out = (float*)d_out;                        // (B, 1000, 8)

    cudaFuncSetAttribute(rpn_post_kernel,
                         cudaFuncAttributeMaxDynamicSharedMemorySize, SMEM_BYTES);
    rpn_post_kernel<<<NB, NT, SMEM_BYTES>>>(obj, reg, anc, out);
}

// round 2
// speedup vs baseline: 1.1787x; 1.1787x over previous
#include <cuda_runtime.h>
#include <math.h>

#define NB 4
#define NA 262144
#define PRE 4000
#define POST 1000
#define SORTN 4096
#define NT 1024
#define HBINS 65536
#define HCTA 128          // CTAs per batch for histogram/compact passes
#define HTHR 256

static __device__ const float NMS_TH = 0.3f;
static __device__ const float AUG = 0.2f;

// ---- global scratch (static, no allocation) ----
__device__ unsigned g_hist[NB][HBINS];
__device__ unsigned g_hist2[NB][HBINS];
__device__ unsigned g_b16[NB];
__device__ unsigned g_need[NB];
__device__ unsigned g_T[NB];
__device__ unsigned long long g_keys[NB][SORTN];
__device__ int g_cnt[NB];

__device__ __forceinline__ unsigned mapf(float v) {
    unsigned u = __float_as_uint(v);
    return (u & 0x80000000u) ? ~u : (u | 0x80000000u);
}

__device__ __forceinline__ void decode_box(const float* __restrict__ rg,
                                           const float* __restrict__ an,
                                           float* bx) {
    float xa = an[0], ya = an[1], za = an[2];
    float wa = an[3], la = an[4], ha = an[5], ra = an[6];
    float dx = rg[0], dy = rg[1], dz = rg[2];
    float dw = rg[3], dl = rg[4], dh = rg[5], dr = rg[6];
    float diag = sqrtf(wa * wa + la * la);
    bx[0] = dx * diag + xa;
    bx[1] = dy * diag + ya;
    bx[2] = dz * ha + za;
    bx[3] = expf(dw) * wa;
    bx[4] = expf(dl) * la;
    bx[5] = expf(dh) * ha;
    bx[6] = dr + ra;
}

// ================= K0: zero scratch =================
__global__ void k_zero() {
    unsigned* h1 = &g_hist[0][0];
    unsigned* h2 = &g_hist2[0][0];
    const int n = NB * HBINS;
    for (int i = blockIdx.x * blockDim.x + threadIdx.x; i < n;
         i += gridDim.x * blockDim.x) {
        h1[i] = 0u;
        h2[i] = 0u;
    }
    if (blockIdx.x == 0 && threadIdx.x < NB) g_cnt[threadIdx.x] = 0;
}

// ================= K1: hi-16 histogram (chip-wide) =================
__global__ void k_hist_hi(const float* __restrict__ obj) {
    const int b = blockIdx.x / HCTA;
    const int c = blockIdx.x % HCTA;
    const float4* o4 = (const float4*)(obj + (size_t)b * NA) + (size_t)c * (NA / HCTA / 4);
    for (int i = threadIdx.x; i < NA / HCTA / 4; i += HTHR) {
        float4 v = o4[i];
        atomicAdd(&g_hist[b][mapf(v.x) >> 16], 1u);
        atomicAdd(&g_hist[b][mapf(v.y) >> 16], 1u);
        atomicAdd(&g_hist[b][mapf(v.z) >> 16], 1u);
        atomicAdd(&g_hist[b][mapf(v.w) >> 16], 1u);
    }
}

// ================= K2: find hi-16 bucket + residual need =================
__global__ void __launch_bounds__(NT) k_scan_hi() {
    const int b = blockIdx.x;
    __shared__ unsigned ssum[NT];
    const unsigned* h = g_hist[b];
    const int base = threadIdx.x * (HBINS / NT);
    unsigned csum = 0;
    for (int k = 0; k < HBINS / NT; ++k) csum += h[base + k];
    unsigned orig = csum;
    ssum[threadIdx.x] = csum;
    __syncthreads();
    for (int d = 1; d < NT; d <<= 1) {
        unsigned v = (threadIdx.x + d < NT) ? ssum[threadIdx.x + d] : 0u;
        __syncthreads();
        ssum[threadIdx.x] += v;
        __syncthreads();
    }
    unsigned inc = ssum[threadIdx.x];
    unsigned exc = inc - orig;
    if (exc < PRE && inc >= PRE) {
        unsigned run = exc;
        for (int k = HBINS / NT - 1; k >= 0; --k) {
            unsigned cc = h[base + k];
            run += cc;
            if (run >= PRE) {
                g_b16[b] = (unsigned)(base + k);
                g_need[b] = PRE - (run - cc);
                break;
            }
        }
    }
}

// ================= K3: lo-16 histogram for the selected bucket =================
__global__ void k_hist_lo(const float* __restrict__ obj) {
    const int b = blockIdx.x / HCTA;
    const int c = blockIdx.x % HCTA;
    const unsigned bsel = g_b16[b];
    const float4* o4 = (const float4*)(obj + (size_t)b * NA) + (size_t)c * (NA / HCTA / 4);
    for (int i = threadIdx.x; i < NA / HCTA / 4; i += HTHR) {
        float4 v = o4[i];
        unsigned u0 = mapf(v.x), u1 = mapf(v.y), u2 = mapf(v.z), u3 = mapf(v.w);
        if ((u0 >> 16) == bsel) atomicAdd(&g_hist2[b][u0 & 0xFFFFu], 1u);
        if ((u1 >> 16) == bsel) atomicAdd(&g_hist2[b][u1 & 0xFFFFu], 1u);
        if ((u2 >> 16) == bsel) atomicAdd(&g_hist2[b][u2 & 0xFFFFu], 1u);
        if ((u3 >> 16) == bsel) atomicAdd(&g_hist2[b][u3 & 0xFFFFu], 1u);
    }
}

// ================= K4: exact 32-bit threshold =================
__global__ void __launch_bounds__(NT) k_scan_lo() {
    const int b = blockIdx.x;
    __shared__ unsigned ssum[NT];
    const unsigned* h = g_hist2[b];
    const unsigned need = g_need[b];
    const int base = threadIdx.x * (HBINS / NT);
    unsigned csum = 0;
    for (int k = 0; k < HBINS / NT; ++k) csum += h[base + k];
    unsigned orig = csum;
    ssum[threadIdx.x] = csum;
    __syncthreads();
    for (int d = 1; d < NT; d <<= 1) {
        unsigned v = (threadIdx.x + d < NT) ? ssum[threadIdx.x + d] : 0u;
        __syncthreads();
        ssum[threadIdx.x] += v;
        __syncthreads();
    }
    unsigned inc = ssum[threadIdx.x];
    unsigned exc = inc - orig;
    if (exc < need && inc >= need) {
        unsigned run = exc;
        for (int k = HBINS / NT - 1; k >= 0; --k) {
            unsigned cc = h[base + k];
            run += cc;
            if (run >= need) {
                g_T[b] = (g_b16[b] << 16) | (unsigned)(base + k);
                break;
            }
        }
    }
}

// ================= K5: compact candidates >= T (warp-aggregated) =================
__global__ void k_compact(const float* __restrict__ obj) {
    const int b = blockIdx.x / HCTA;
    const int c = blockIdx.x % HCTA;
    const unsigned T = g_T[b];
    const int lane = threadIdx.x & 31;
    const float4* o4 = (const float4*)(obj + (size_t)b * NA) + (size_t)c * (NA / HCTA / 4);
    for (int i = threadIdx.x; i < NA / HCTA / 4; i += HTHR) {
        float4 v = o4[i];
        unsigned uu[4] = {mapf(v.x), mapf(v.y), mapf(v.z), mapf(v.w)};
        int e0 = (c * (NA / HCTA / 4) + i) * 4;
        #pragma unroll
        for (int q = 0; q < 4; ++q) {
            bool has = uu[q] >= T;
            unsigned mk = __ballot_sync(0xffffffffu, has);
            if (mk) {
                int ldr = __ffs(mk) - 1;
                int bpos = 0;
                if (lane == ldr) bpos = atomicAdd(&g_cnt[b], __popc(mk));
                bpos = __shfl_sync(0xffffffffu, bpos, ldr);
                int pos = bpos + __popc(mk & ((1u << lane) - 1u));
                if (has && pos < SORTN)
                    g_keys[b][pos] =
                        ((unsigned long long)uu[q] << 32) | (unsigned)(~(e0 + q));
            }
        }
    }
}

// ================= K6: sort + decode + windowed NMS + output =================
// smem layout (bytes)
static const int OFF_KEYS = 0;                        // 4096 * u64 = 32768
static const int OFF_GEO  = OFF_KEYS + SORTN * 8;     // 7*4096*4  = 114688
static const int OFF_SIDX = OFF_GEO + 7 * SORTN * 4;  // 16384
static const int OFF_ORD  = OFF_SIDX + SORTN * 4;     // POST ints = 4000 -> 4096
static const int OFF_KEEP = OFF_ORD + 4096;           // 4096
static const int OFF_WM   = OFF_KEEP + SORTN;         // 32 * 4
static const int OFF_WL   = OFF_WM + 128;             // 32 * 4
static const int OFF_CNT  = OFF_WL + 128;
static const int SMEM_BYTES = OFF_CNT + 64;

__global__ void __launch_bounds__(NT) rpn_main(
    const float* __restrict__ obj,
    const float* __restrict__ reg,
    const float* __restrict__ anc,
    float* __restrict__ out)
{
    extern __shared__ unsigned char smem[];
    unsigned long long* keys = (unsigned long long*)(smem + OFF_KEYS);
    float* lox = (float*)(smem + OFF_GEO);
    float* loy = lox + SORTN;
    float* loz = loy + SORTN;
    float* hix = loz + SORTN;
    float* hiy = hix + SORTN;
    float* hiz = hiy + SORTN;
    float* vol = hiz + SORTN;
    int* sidx = (int*)(smem + OFF_SIDX);
    int* order = (int*)(smem + OFF_ORD);
    unsigned char* keep = (unsigned char*)(smem + OFF_KEEP);
    unsigned* winmask = (unsigned*)(smem + OFF_WM);
    int* win_list = (int*)(smem + OFF_WL);
    int* cnts = (int*)(smem + OFF_CNT);  // [1]=kept count, [4]=window kept count

    const int b = blockIdx.x;
    const int tid = threadIdx.x;
    const float* objb = obj + (size_t)b * NA;

    // ---- load compacted keys, pad with 0 ----
    int cc = g_cnt[b];
    if (cc > SORTN) cc = SORTN;
    for (int i = tid; i < SORTN; i += NT)
        keys[i] = (i < cc) ? g_keys[b][i] : 0ull;
    __syncthreads();

    // ---- bitonic sort descending (ties -> lower index first) ----
    for (int k = 2; k <= SORTN; k <<= 1) {
        for (int j = k >> 1; j > 0; j >>= 1) {
            for (int t = tid; t < SORTN; t += NT) {
                int ixj = t ^ j;
                if (ixj > t) {
                    unsigned long long a = keys[t];
                    unsigned long long c2 = keys[ixj];
                    bool up = ((t & k) == 0);
                    if (up ? (a < c2) : (a > c2)) {
                        keys[t] = c2;
                        keys[ixj] = a;
                    }
                }
            }
            __syncthreads();
        }
    }

    // ---- decode top-4000, build augmented AABBs ----
    for (int r = tid; r < PRE; r += NT) {
        int idx = (int)(~(unsigned)(keys[r] & 0xFFFFFFFFull));
        sidx[r] = idx;
        const float* rg = reg + ((size_t)b * NA + idx) * 7;
        const float* an = anc + ((size_t)b * NA + idx) * 7;
        float bx[7];
        decode_box(rg, an, bx);
        float sx = fmaxf(bx[3], AUG);
        float sy = fmaxf(bx[4], AUG);
        float sz = fmaxf(bx[5], AUG);
        lox[r] = bx[0] - sx * 0.5f;
        loy[r] = bx[1] - sy * 0.5f;
        loz[r] = bx[2];
        hix[r] = bx[0] + sx * 0.5f;
        hiy[r] = bx[1] + sy * 0.5f;
        hiz[r] = bx[2] + sz;
        vol[r] = sx * sy * sz;
        keep[r] = 1;
    }
    if (tid == 0) cnts[1] = 0;
    __syncthreads();

    // ---- windowed greedy NMS (W=32), early stop at 1000 kept ----
    for (int w0 = 0; w0 < PRE; w0 += 32) {
        // phase A0: all 1024 threads test one intra-window pair each
        {
            int il = tid >> 5, jl = tid & 31;
            int bi = w0 + il, bj = w0 + jl;
            bool sup = false;
            if (jl > il) {
                float dxx = fminf(hix[bi], hix[bj]) - fmaxf(lox[bi], lox[bj]);
                if (dxx > 0.f) {
                    float dyy = fminf(hiy[bi], hiy[bj]) - fmaxf(loy[bi], loy[bj]);
                    if (dyy > 0.f) {
                        float dzz = fminf(hiz[bi], hiz[bj]) - fmaxf(loz[bi], loz[bj]);
                        if (dzz > 0.f) {
                            float inter = dxx * dyy * dzz;
                            float iou = inter / fmaxf(vol[bi] + vol[bj] - inter, 1e-8f);
                            sup = iou > NMS_TH;
                        }
                    }
                }
            }
            unsigned mm = __ballot_sync(0xffffffffu, sup);
            if (jl == 0) winmask[il] = mm;
        }
        __syncthreads();
        // phase A1: warp 0 finalizes window keep bits via scalar bit-walk
        if (tid < 32) {
            bool kj = keep[w0 + tid] != 0;
            unsigned alive = __ballot_sync(0xffffffffu, kj);
            #pragma unroll
            for (int l = 0; l < 32; ++l)
                if ((alive >> l) & 1u) alive &= ~winmask[l];
            bool mk = (alive >> tid) & 1u;
            keep[w0 + tid] = mk ? 1 : 0;
            int pc = __popc(alive & ((1u << tid) - 1u));
            int kc = cnts[1];
            if (mk) {
                win_list[pc] = w0 + tid;
                if (kc + pc < POST) order[kc + pc] = w0 + tid;
            }
            if (tid == 0) {
                cnts[4] = __popc(alive);
                cnts[1] = kc + __popc(alive);
            }
        }
        __syncthreads();
        int mcount = cnts[4];
        // phase B: apply window's kept boxes to the tail
        for (int j = w0 + 32 + tid; j < PRE; j += NT) {
            if (!keep[j]) continue;
            float jlx = lox[j], jly = loy[j], jlz = loz[j];
            float jhx = hix[j], jhy = hiy[j], jhz = hiz[j], jv = vol[j];
            for (int t = 0; t < mcount; ++t) {
                int ii = win_list[t];
                float dxx = fminf(jhx, hix[ii]) - fmaxf(jlx, lox[ii]);
                if (dxx <= 0.f) continue;
                float dyy = fminf(jhy, hiy[ii]) - fmaxf(jly, loy[ii]);
                if (dyy <= 0.f) continue;
                float dzz = fminf(jhz, hiz[ii]) - fmaxf(jlz, loz[ii]);
                if (dzz <= 0.f) continue;
                float inter = dxx * dyy * dzz;
                float iou = inter / fmaxf(jv + vol[ii] - inter, 1e-8f);
                if (iou > NMS_TH) { keep[j] = 0; break; }
            }
        }
        __syncthreads();
        if (cnts[1] >= POST) break;
    }
    __syncthreads();

    // ---- output: first min(kept,1000) rows, zero the rest ----
    int nk = cnts[1];
    if (nk > POST) nk = POST;
    float* outb = out + (size_t)b * POST * 8;
    for (int r = tid; r < POST; r += NT) {
        float row[8];
        if (r < nk) {
            int rr = order[r];
            int idx = sidx[rr];
            const float* rg = reg + ((size_t)b * NA + idx) * 7;
            const float* an = anc + ((size_t)b * NA + idx) * 7;
            decode_box(rg, an, row);
            float lg = objb[idx];
            row[7] = 1.0f / (1.0f + expf(-lg));
        } else {
            #pragma unroll
            for (int c = 0; c < 8; ++c) row[c] = 0.f;
        }
        #pragma unroll
        for (int c = 0; c < 8; ++c) outb[r * 8 + c] = row[c];
    }
}

extern "C" void kernel_launch(void* const* d_in, const int* in_sizes, int n_in,
                              void* d_out, int out_size) {
    const float* obj = (const float*)d_in[0];
    const float* reg = (const float*)d_in[1];
    const float* anc = (const float*)d_in[2];
    float* out = (float*)d_out;

    cudaFuncSetAttribute(rpn_main,
                         cudaFuncAttributeMaxDynamicSharedMemorySize, SMEM_BYTES);

    k_zero<<<256, 256>>>();
    k_hist_hi<<<NB * HCTA, HTHR>>>(obj);
    k_scan_hi<<<NB, NT>>>();
    k_hist_lo<<<NB * HCTA, HTHR>>>(obj);
    k_scan_lo<<<NB, NT>>>();
    k_compact<<<NB * HCTA, HTHR>>>(obj);
    rpn_main<<<NB, NT, SMEM_BYTES>>>(obj, reg, anc, out);
}

// round 3
// speedup vs baseline: 1.2915x; 1.0957x over previous
#include <cuda_runtime.h>
#include <math.h>

#define NB 4
#define NA 262144
#define PRE 4000
#define POST 1000
#define SORTN 4096
#define NT 1024
#define HBINS 65536
#define HCTA 128
#define HTHR 256
#define RCTA 16       // rank CTAs per batch
#define RTHR 256

static __device__ const float NMS_TH = 0.3f;
static __device__ const float AUG = 0.2f;

// ---- global scratch ----
__device__ unsigned g_hist[NB][HBINS];
__device__ unsigned g_hist2[NB][HBINS];
__device__ unsigned g_b16[NB];
__device__ unsigned g_need[NB];
__device__ unsigned g_T[NB];
__device__ unsigned long long g_keys[NB][SORTN];
__device__ int g_cnt[NB];
__device__ float g_geo[NB][7][SORTN];      // lox,loy,loz,hix,hiy,hiz,vol at sorted rank
__device__ float g_box[NB][SORTN][7];      // decoded raw box at sorted rank
__device__ float g_score[NB][SORTN];       // sigmoid score at sorted rank
__device__ int g_order[NB][POST];
__device__ int g_nk[NB];

__device__ __forceinline__ unsigned mapf(float v) {
    unsigned u = __float_as_uint(v);
    return (u & 0x80000000u) ? ~u : (u | 0x80000000u);
}
__device__ __forceinline__ float unmapf(unsigned m) {
    return __uint_as_float((m & 0x80000000u) ? (m & 0x7FFFFFFFu) : ~m);
}

__device__ __forceinline__ void decode_box(const float* __restrict__ rg,
                                           const float* __restrict__ an,
                                           float* bx) {
    float xa = an[0], ya = an[1], za = an[2];
    float wa = an[3], la = an[4], ha = an[5], ra = an[6];
    float diag = sqrtf(wa * wa + la * la);
    bx[0] = rg[0] * diag + xa;
    bx[1] = rg[1] * diag + ya;
    bx[2] = rg[2] * ha + za;
    bx[3] = expf(rg[3]) * wa;
    bx[4] = expf(rg[4]) * la;
    bx[5] = expf(rg[5]) * ha;
    bx[6] = rg[6] + ra;
}

// ================= K0: zero scratch =================
__global__ void k_zero() {
    unsigned* h1 = &g_hist[0][0];
    unsigned* h2 = &g_hist2[0][0];
    const int n = NB * HBINS;
    for (int i = blockIdx.x * blockDim.x + threadIdx.x; i < n;
         i += gridDim.x * blockDim.x) {
        h1[i] = 0u;
        h2[i] = 0u;
    }
    if (blockIdx.x == 0 && threadIdx.x < NB) g_cnt[threadIdx.x] = 0;
}

// ================= K1: hi-16 histogram =================
__global__ void k_hist_hi(const float* __restrict__ obj) {
    const int b = blockIdx.x / HCTA;
    const int c = blockIdx.x % HCTA;
    const float4* o4 = (const float4*)(obj + (size_t)b * NA) + (size_t)c * (NA / HCTA / 4);
    for (int i = threadIdx.x; i < NA / HCTA / 4; i += HTHR) {
        float4 v = o4[i];
        atomicAdd(&g_hist[b][mapf(v.x) >> 16], 1u);
        atomicAdd(&g_hist[b][mapf(v.y) >> 16], 1u);
        atomicAdd(&g_hist[b][mapf(v.z) >> 16], 1u);
        atomicAdd(&g_hist[b][mapf(v.w) >> 16], 1u);
    }
}

// ================= K2: hi-16 bucket + residual need =================
__global__ void __launch_bounds__(NT) k_scan_hi() {
    const int b = blockIdx.x;
    __shared__ unsigned ssum[NT];
    const unsigned* h = g_hist[b];
    const int base = threadIdx.x * (HBINS / NT);
    unsigned csum = 0;
    for (int k = 0; k < HBINS / NT; ++k) csum += h[base + k];
    unsigned orig = csum;
    ssum[threadIdx.x] = csum;
    __syncthreads();
    for (int d = 1; d < NT; d <<= 1) {
        unsigned v = (threadIdx.x + d < NT) ? ssum[threadIdx.x + d] : 0u;
        __syncthreads();
        ssum[threadIdx.x] += v;
        __syncthreads();
    }
    unsigned inc = ssum[threadIdx.x];
    unsigned exc = inc - orig;
    if (exc < PRE && inc >= PRE) {
        unsigned run = exc;
        for (int k = HBINS / NT - 1; k >= 0; --k) {
            unsigned cc = h[base + k];
            run += cc;
            if (run >= PRE) {
                g_b16[b] = (unsigned)(base + k);
                g_need[b] = PRE - (run - cc);
                break;
            }
        }
    }
}

// ================= K3: lo-16 histogram =================
__global__ void k_hist_lo(const float* __restrict__ obj) {
    const int b = blockIdx.x / HCTA;
    const int c = blockIdx.x % HCTA;
    const unsigned bsel = g_b16[b];
    const float4* o4 = (const float4*)(obj + (size_t)b * NA) + (size_t)c * (NA / HCTA / 4);
    for (int i = threadIdx.x; i < NA / HCTA / 4; i += HTHR) {
        float4 v = o4[i];
        unsigned u0 = mapf(v.x), u1 = mapf(v.y), u2 = mapf(v.z), u3 = mapf(v.w);
        if ((u0 >> 16) == bsel) atomicAdd(&g_hist2[b][u0 & 0xFFFFu], 1u);
        if ((u1 >> 16) == bsel) atomicAdd(&g_hist2[b][u1 & 0xFFFFu], 1u);
        if ((u2 >> 16) == bsel) atomicAdd(&g_hist2[b][u2 & 0xFFFFu], 1u);
        if ((u3 >> 16) == bsel) atomicAdd(&g_hist2[b][u3 & 0xFFFFu], 1u);
    }
}

// ================= K4: exact threshold =================
__global__ void __launch_bounds__(NT) k_scan_lo() {
    const int b = blockIdx.x;
    __shared__ unsigned ssum[NT];
    const unsigned* h = g_hist2[b];
    const unsigned need = g_need[b];
    const int base = threadIdx.x * (HBINS / NT);
    unsigned csum = 0;
    for (int k = 0; k < HBINS / NT; ++k) csum += h[base + k];
    unsigned orig = csum;
    ssum[threadIdx.x] = csum;
    __syncthreads();
    for (int d = 1; d < NT; d <<= 1) {
        unsigned v = (threadIdx.x + d < NT) ? ssum[threadIdx.x + d] : 0u;
        __syncthreads();
        ssum[threadIdx.x] += v;
        __syncthreads();
    }
    unsigned inc = ssum[threadIdx.x];
    unsigned exc = inc - orig;
    if (exc < need && inc >= need) {
        unsigned run = exc;
        for (int k = HBINS / NT - 1; k >= 0; --k) {
            unsigned cc = h[base + k];
            run += cc;
            if (run >= need) {
                g_T[b] = (g_b16[b] << 16) | (unsigned)(base + k);
                break;
            }
        }
    }
}

// ================= K5: compact candidates >= T =================
__global__ void k_compact(const float* __restrict__ obj) {
    const int b = blockIdx.x / HCTA;
    const int c = blockIdx.x % HCTA;
    const unsigned T = g_T[b];
    const int lane = threadIdx.x & 31;
    const float4* o4 = (const float4*)(obj + (size_t)b * NA) + (size_t)c * (NA / HCTA / 4);
    for (int i = threadIdx.x; i < NA / HCTA / 4; i += HTHR) {
        float4 v = o4[i];
        unsigned uu[4] = {mapf(v.x), mapf(v.y), mapf(v.z), mapf(v.w)};
        int e0 = (c * (NA / HCTA / 4) + i) * 4;
        #pragma unroll
        for (int q = 0; q < 4; ++q) {
            bool has = uu[q] >= T;
            unsigned mk = __ballot_sync(0xffffffffu, has);
            if (mk) {
                int ldr = __ffs(mk) - 1;
                int bpos = 0;
                if (lane == ldr) bpos = atomicAdd(&g_cnt[b], __popc(mk));
                bpos = __shfl_sync(0xffffffffu, bpos, ldr);
                int pos = bpos + __popc(mk & ((1u << lane) - 1u));
                if (has && pos < SORTN)
                    g_keys[b][pos] =
                        ((unsigned long long)uu[q] << 32) | (unsigned)(~(e0 + q));
            }
        }
    }
}

// ================= K6: rank (exact stable sort) + decode + scatter =================
__global__ void __launch_bounds__(RTHR) k_rank(
    const float* __restrict__ reg, const float* __restrict__ anc)
{
    const int b = blockIdx.x / RCTA;
    const int c = blockIdx.x % RCTA;
    __shared__ unsigned long long sk[SORTN];
    int cc = g_cnt[b];
    if (cc > SORTN) cc = SORTN;
    for (int i = threadIdx.x; i < SORTN; i += RTHR)
        sk[i] = (i < cc) ? g_keys[b][i] : 0ull;
    __syncthreads();

    const int i = c * RTHR + threadIdx.x;
    if (i >= cc) return;
    const unsigned long long me = sk[i];
    int rank = 0;
    #pragma unroll 8
    for (int j = 0; j < cc; ++j) rank += (sk[j] > me);

    // scatter decode to rank slot
    if (rank < PRE) {
        int idx = (int)(~(unsigned)(me & 0xFFFFFFFFull));
        const float* rg = reg + ((size_t)b * NA + idx) * 7;
        const float* an = anc + ((size_t)b * NA + idx) * 7;
        float bx[7];
        decode_box(rg, an, bx);
        #pragma unroll
        for (int q = 0; q < 7; ++q) g_box[b][rank][q] = bx[q];
        float lg = unmapf((unsigned)(me >> 32));
        g_score[b][rank] = 1.0f / (1.0f + expf(-lg));
        float sx = fmaxf(bx[3], AUG);
        float sy = fmaxf(bx[4], AUG);
        float sz = fmaxf(bx[5], AUG);
        g_geo[b][0][rank] = bx[0] - sx * 0.5f;
        g_geo[b][1][rank] = bx[1] - sy * 0.5f;
        g_geo[b][2][rank] = bx[2];
        g_geo[b][3][rank] = bx[0] + sx * 0.5f;
        g_geo[b][4][rank] = bx[1] + sy * 0.5f;
        g_geo[b][5][rank] = bx[2] + sz;
        g_geo[b][6][rank] = sx * sy * sz;
    }
}

// ================= K7: windowed greedy NMS =================
static const int OFF_GEO  = 0;                        // 7*4096*4 = 114688
static const int OFF_KEEP = OFF_GEO + 7 * SORTN * 4;  // 4096
static const int OFF_ORD  = OFF_KEEP + SORTN;         // 1024*4
static const int OFF_WM   = OFF_ORD + 4096;           // 128
static const int OFF_WL   = OFF_WM + 128;             // 128
static const int OFF_CNT  = OFF_WL + 128;
static const int SMEM_BYTES = OFF_CNT + 64;

__global__ void __launch_bounds__(NT) k_nms() {
    extern __shared__ unsigned char smem[];
    float* lox = (float*)(smem + OFF_GEO);
    float* loy = lox + SORTN;
    float* loz = loy + SORTN;
    float* hix = loz + SORTN;
    float* hiy = hix + SORTN;
    float* hiz = hiy + SORTN;
    float* vol = hiz + SORTN;
    unsigned char* keep = (unsigned char*)(smem + OFF_KEEP);
    int* order = (int*)(smem + OFF_ORD);
    unsigned* winmask = (unsigned*)(smem + OFF_WM);
    int* win_list = (int*)(smem + OFF_WL);
    int* cnts = (int*)(smem + OFF_CNT);

    const int b = blockIdx.x;
    const int tid = threadIdx.x;

    // coalesced load of geo (float4)
    {
        const float4* src = (const float4*)&g_geo[b][0][0];
        float4* dst = (float4*)lox;
        for (int i = tid; i < 7 * SORTN / 4; i += NT) dst[i] = src[i];
    }
    for (int i = tid; i < SORTN; i += NT) keep[i] = 1;
    if (tid == 0) cnts[1] = 0;
    __syncthreads();

    for (int w0 = 0; w0 < PRE; w0 += 32) {
        // A0: 1024 threads = full 32x32 pair matrix
        {
            int il = tid >> 5, jl = tid & 31;
            int bi = w0 + il, bj = w0 + jl;
            bool sup = false;
            if (jl > il) {
                float dxx = fminf(hix[bi], hix[bj]) - fmaxf(lox[bi], lox[bj]);
                if (dxx > 0.f) {
                    float dyy = fminf(hiy[bi], hiy[bj]) - fmaxf(loy[bi], loy[bj]);
                    if (dyy > 0.f) {
                        float dzz = fminf(hiz[bi], hiz[bj]) - fmaxf(loz[bi], loz[bj]);
                        if (dzz > 0.f) {
                            float inter = dxx * dyy * dzz;
                            float iou = inter / fmaxf(vol[bi] + vol[bj] - inter, 1e-8f);
                            sup = iou > NMS_TH;
                        }
                    }
                }
            }
            unsigned mm = __ballot_sync(0xffffffffu, sup);
            if (jl == 0) winmask[il] = mm;
        }
        __syncthreads();
        // A1: warp 0 bit-walk
        if (tid < 32) {
            bool kj = keep[w0 + tid] != 0;
            unsigned alive = __ballot_sync(0xffffffffu, kj);
            #pragma unroll
            for (int l = 0; l < 32; ++l)
                if ((alive >> l) & 1u) alive &= ~winmask[l];
            bool mk = (alive >> tid) & 1u;
            keep[w0 + tid] = mk ? 1 : 0;
            int pc = __popc(alive & ((1u << tid) - 1u));
            int kc = cnts[1];
            if (mk) {
                win_list[pc] = w0 + tid;
                if (kc + pc < POST) order[kc + pc] = w0 + tid;
            }
            if (tid == 0) {
                cnts[4] = __popc(alive);
                cnts[1] = kc + __popc(alive);
            }
        }
        __syncthreads();
        int mcount = cnts[4];
        // B: apply kept boxes to tail
        for (int j = w0 + 32 + tid; j < PRE; j += NT) {
            if (!keep[j]) continue;
            float jlx = lox[j], jly = loy[j], jlz = loz[j];
            float jhx = hix[j], jhy = hiy[j], jhz = hiz[j], jv = vol[j];
            for (int t = 0; t < mcount; ++t) {
                int ii = win_list[t];
                float dxx = fminf(jhx, hix[ii]) - fmaxf(jlx, lox[ii]);
                if (dxx <= 0.f) continue;
                float dyy = fminf(jhy, hiy[ii]) - fmaxf(jly, loy[ii]);
                if (dyy <= 0.f) continue;
                float dzz = fminf(jhz, hiz[ii]) - fmaxf(jlz, loz[ii]);
                if (dzz <= 0.f) continue;
                float inter = dxx * dyy * dzz;
                float iou = inter / fmaxf(jv + vol[ii] - inter, 1e-8f);
                if (iou > NMS_TH) { keep[j] = 0; break; }
            }
        }
        __syncthreads();
        if (cnts[1] >= POST) break;
    }
    __syncthreads();

    int nk = cnts[1];
    if (nk > POST) nk = POST;
    for (int r = tid; r < nk; r += NT) g_order[b][r] = order[r];
    if (tid == 0) g_nk[b] = nk;
}

// ================= K8: output =================
__global__ void k_out(float* __restrict__ out) {
    const int stride = gridDim.x * blockDim.x;
    for (int t = blockIdx.x * blockDim.x + threadIdx.x; t < NB * POST; t += stride) {
        int b = t / POST;
        int r = t % POST;
        float row[8];
        if (r < g_nk[b]) {
            int rr = g_order[b][r];
            #pragma unroll
            for (int q = 0; q < 7; ++q) row[q] = g_box[b][rr][q];
            row[7] = g_score[b][rr];
        } else {
            #pragma unroll
            for (int q = 0; q < 8; ++q) row[q] = 0.f;
        }
        float4* o4 = (float4*)(out + (size_t)t * 8);
        o4[0] = make_float4(row[0], row[1], row[2], row[3]);
        o4[1] = make_float4(row[4], row[5], row[6], row[7]);
    }
}

extern "C" void kernel_launch(void* const* d_in, const int* in_sizes, int n_in,
                              void* d_out, int out_size) {
    const float* obj = (const float*)d_in[0];
    const float* reg = (const float*)d_in[1];
    const float* anc = (const float*)d_in[2];
    float* out = (float*)d_out;

    cudaFuncSetAttribute(k_nms,
                         cudaFuncAttributeMaxDynamicSharedMemorySize, SMEM_BYTES);

    k_zero<<<256, 256>>>();
    k_hist_hi<<<NB * HCTA, HTHR>>>(obj);
    k_scan_hi<<<NB, NT>>>();
    k_hist_lo<<<NB * HCTA, HTHR>>>(obj);
    k_scan_lo<<<NB, NT>>>();
    k_compact<<<NB * HCTA, HTHR>>>(obj);
    k_rank<<<NB * RCTA, RTHR>>>(reg, anc);
    k_nms<<<NB, NT, SMEM_BYTES>>>();
    k_out<<<32, 128>>>(out);
}

// round 4
// speedup vs baseline: 3.4509x; 2.6721x over previous
#include <cuda_runtime.h>
#include <math.h>

#define NB 4
#define NA 262144
#define PRE 4000
#define POST 1000
#define SORTN 4096
#define NT 1024
#define HBINS 65536
#define HCTA 128
#define HTHR 256
#define RCTA 16
#define RTHR 256
#define PCAP 8192

static __device__ const float NMS_TH = 0.3f;
static __device__ const float AUG = 0.2f;

// ---- global scratch ----
__device__ unsigned g_hist[NB][HBINS];
__device__ unsigned g_hist2[NB][HBINS];
__device__ unsigned g_b16[NB];
__device__ unsigned g_need[NB];
__device__ unsigned g_T[NB];
__device__ unsigned long long g_keys[NB][SORTN];
__device__ int g_cnt[NB];
__device__ float g_geo[NB][7][SORTN];     // lox,loy,loz,hix,hiy,hiz,vol at rank
__device__ float g_box[NB][SORTN][7];     // decoded box at rank
__device__ float g_score[NB][SORTN];      // sigmoid score at rank
__device__ unsigned g_pairs[NB][PCAP];    // conflict pairs (i<<16)|j
__device__ int g_pcnt[NB];
__device__ int g_order[NB][POST];
__device__ int g_nk[NB];

__device__ __forceinline__ unsigned mapf(float v) {
    unsigned u = __float_as_uint(v);
    return (u & 0x80000000u) ? ~u : (u | 0x80000000u);
}
__device__ __forceinline__ float unmapf(unsigned m) {
    return __uint_as_float((m & 0x80000000u) ? (m & 0x7FFFFFFFu) : ~m);
}

__device__ __forceinline__ void decode_box(const float* __restrict__ rg,
                                           const float* __restrict__ an,
                                           float* bx) {
    float xa = an[0], ya = an[1], za = an[2];
    float wa = an[3], la = an[4], ha = an[5], ra = an[6];
    float diag = sqrtf(wa * wa + la * la);
    bx[0] = rg[0] * diag + xa;
    bx[1] = rg[1] * diag + ya;
    bx[2] = rg[2] * ha + za;
    bx[3] = expf(rg[3]) * wa;
    bx[4] = expf(rg[4]) * la;
    bx[5] = expf(rg[5]) * ha;
    bx[6] = rg[6] + ra;
}

// ================= K0: zero scratch =================
__global__ void k_zero() {
    unsigned* h1 = &g_hist[0][0];
    unsigned* h2 = &g_hist2[0][0];
    const int n = NB * HBINS;
    for (int i = blockIdx.x * blockDim.x + threadIdx.x; i < n;
         i += gridDim.x * blockDim.x) {
        h1[i] = 0u;
        h2[i] = 0u;
    }
    if (blockIdx.x == 0 && threadIdx.x < NB) {
        g_cnt[threadIdx.x] = 0;
        g_pcnt[threadIdx.x] = 0;
    }
}

// ================= K1: hi-16 histogram =================
__global__ void k_hist_hi(const float* __restrict__ obj) {
    const int b = blockIdx.x / HCTA;
    const int c = blockIdx.x % HCTA;
    const float4* o4 = (const float4*)(obj + (size_t)b * NA) + (size_t)c * (NA / HCTA / 4);
    for (int i = threadIdx.x; i < NA / HCTA / 4; i += HTHR) {
        float4 v = o4[i];
        atomicAdd(&g_hist[b][mapf(v.x) >> 16], 1u);
        atomicAdd(&g_hist[b][mapf(v.y) >> 16], 1u);
        atomicAdd(&g_hist[b][mapf(v.z) >> 16], 1u);
        atomicAdd(&g_hist[b][mapf(v.w) >> 16], 1u);
    }
}

// ================= K2: hi-16 bucket + residual need =================
__global__ void __launch_bounds__(NT) k_scan_hi() {
    const int b = blockIdx.x;
    __shared__ unsigned ssum[NT];
    const unsigned* h = g_hist[b];
    const int base = threadIdx.x * (HBINS / NT);
    unsigned csum = 0;
    for (int k = 0; k < HBINS / NT; ++k) csum += h[base + k];
    unsigned orig = csum;
    ssum[threadIdx.x] = csum;
    __syncthreads();
    for (int d = 1; d < NT; d <<= 1) {
        unsigned v = (threadIdx.x + d < NT) ? ssum[threadIdx.x + d] : 0u;
        __syncthreads();
        ssum[threadIdx.x] += v;
        __syncthreads();
    }
    unsigned inc = ssum[threadIdx.x];
    unsigned exc = inc - orig;
    if (exc < PRE && inc >= PRE) {
        unsigned run = exc;
        for (int k = HBINS / NT - 1; k >= 0; --k) {
            unsigned cc = h[base + k];
            run += cc;
            if (run >= PRE) {
                g_b16[b] = (unsigned)(base + k);
                g_need[b] = PRE - (run - cc);
                break;
            }
        }
    }
}

// ================= K3: lo-16 histogram =================
__global__ void k_hist_lo(const float* __restrict__ obj) {
    const int b = blockIdx.x / HCTA;
    const int c = blockIdx.x % HCTA;
    const unsigned bsel = g_b16[b];
    const float4* o4 = (const float4*)(obj + (size_t)b * NA) + (size_t)c * (NA / HCTA / 4);
    for (int i = threadIdx.x; i < NA / HCTA / 4; i += HTHR) {
        float4 v = o4[i];
        unsigned u0 = mapf(v.x), u1 = mapf(v.y), u2 = mapf(v.z), u3 = mapf(v.w);
        if ((u0 >> 16) == bsel) atomicAdd(&g_hist2[b][u0 & 0xFFFFu], 1u);
        if ((u1 >> 16) == bsel) atomicAdd(&g_hist2[b][u1 & 0xFFFFu], 1u);
        if ((u2 >> 16) == bsel) atomicAdd(&g_hist2[b][u2 & 0xFFFFu], 1u);
        if ((u3 >> 16) == bsel) atomicAdd(&g_hist2[b][u3 & 0xFFFFu], 1u);
    }
}

// ================= K4: exact threshold =================
__global__ void __launch_bounds__(NT) k_scan_lo() {
    const int b = blockIdx.x;
    __shared__ unsigned ssum[NT];
    const unsigned* h = g_hist2[b];
    const unsigned need = g_need[b];
    const int base = threadIdx.x * (HBINS / NT);
    unsigned csum = 0;
    for (int k = 0; k < HBINS / NT; ++k) csum += h[base + k];
    unsigned orig = csum;
    ssum[threadIdx.x] = csum;
    __syncthreads();
    for (int d = 1; d < NT; d <<= 1) {
        unsigned v = (threadIdx.x + d < NT) ? ssum[threadIdx.x + d] : 0u;
        __syncthreads();
        ssum[threadIdx.x] += v;
        __syncthreads();
    }
    unsigned inc = ssum[threadIdx.x];
    unsigned exc = inc - orig;
    if (exc < need && inc >= need) {
        unsigned run = exc;
        for (int k = HBINS / NT - 1; k >= 0; --k) {
            unsigned cc = h[base + k];
            run += cc;
            if (run >= need) {
                g_T[b] = (g_b16[b] << 16) | (unsigned)(base + k);
                break;
            }
        }
    }
}

// ================= K5: compact candidates >= T =================
__global__ void k_compact(const float* __restrict__ obj) {
    const int b = blockIdx.x / HCTA;
    const int c = blockIdx.x % HCTA;
    const unsigned T = g_T[b];
    const int lane = threadIdx.x & 31;
    const float4* o4 = (const float4*)(obj + (size_t)b * NA) + (size_t)c * (NA / HCTA / 4);
    for (int i = threadIdx.x; i < NA / HCTA / 4; i += HTHR) {
        float4 v = o4[i];
        unsigned uu[4] = {mapf(v.x), mapf(v.y), mapf(v.z), mapf(v.w)};
        int e0 = (c * (NA / HCTA / 4) + i) * 4;
        #pragma unroll
        for (int q = 0; q < 4; ++q) {
            bool has = uu[q] >= T;
            unsigned mk = __ballot_sync(0xffffffffu, has);
            if (mk) {
                int ldr = __ffs(mk) - 1;
                int bpos = 0;
                if (lane == ldr) bpos = atomicAdd(&g_cnt[b], __popc(mk));
                bpos = __shfl_sync(0xffffffffu, bpos, ldr);
                int pos = bpos + __popc(mk & ((1u << lane) - 1u));
                if (has && pos < SORTN)
                    g_keys[b][pos] =
                        ((unsigned long long)uu[q] << 32) | (unsigned)(~(e0 + q));
            }
        }
    }
}

// ================= K6: rank (exact stable sort) + decode + scatter =================
__global__ void __launch_bounds__(RTHR) k_rank(
    const float* __restrict__ reg, const float* __restrict__ anc)
{
    const int b = blockIdx.x / RCTA;
    const int c = blockIdx.x % RCTA;
    __shared__ unsigned long long sk[SORTN];
    int cc = g_cnt[b];
    if (cc > SORTN) cc = SORTN;
    for (int i = threadIdx.x; i < SORTN; i += RTHR)
        sk[i] = (i < cc) ? g_keys[b][i] : 0ull;
    __syncthreads();

    const int i = c * RTHR + threadIdx.x;
    if (i >= cc) return;
    const unsigned long long me = sk[i];
    int rank = 0;
    #pragma unroll 8
    for (int j = 0; j < cc; ++j) rank += (sk[j] > me);

    if (rank < PRE) {
        int idx = (int)(~(unsigned)(me & 0xFFFFFFFFull));
        const float* rg = reg + ((size_t)b * NA + idx) * 7;
        const float* an = anc + ((size_t)b * NA + idx) * 7;
        float bx[7];
        decode_box(rg, an, bx);
        #pragma unroll
        for (int q = 0; q < 7; ++q) g_box[b][rank][q] = bx[q];
        float lg = unmapf((unsigned)(me >> 32));
        g_score[b][rank] = 1.0f / (1.0f + expf(-lg));
        float sx = fmaxf(bx[3], AUG);
        float sy = fmaxf(bx[4], AUG);
        float sz = fmaxf(bx[5], AUG);
        g_geo[b][0][rank] = bx[0] - sx * 0.5f;
        g_geo[b][1][rank] = bx[1] - sy * 0.5f;
        g_geo[b][2][rank] = bx[2];
        g_geo[b][3][rank] = bx[0] + sx * 0.5f;
        g_geo[b][4][rank] = bx[1] + sy * 0.5f;
        g_geo[b][5][rank] = bx[2] + sz;
        g_geo[b][6][rank] = sx * sy * sz;
    }
}

// ================= K7: chip-wide conflict-pair discovery =================
// grid = NB * 32 jb-blocks * 4 i-chunks, 128 threads
#define JBLK 32
#define ICHK 4
__global__ void __launch_bounds__(128) k_pairs() {
    const int bx = blockIdx.x;
    const int ic = bx & (ICHK - 1);
    const int jb = (bx >> 2) & (JBLK - 1);
    const int b = bx >> 7;
    const int tid = threadIdx.x;

    const int j = jb * 128 + tid;
    const int jmax = min(PRE, jb * 128 + 128);
    const int i_lo = ic * 1024;
    const int i_hi = min(min((ic + 1) * 1024, PRE), jmax);
    if (i_lo >= i_hi) return;

    const bool active = (j < PRE);
    float jlx = 0, jly = 0, jlz = 0, jhx = 0, jhy = 0, jhz = 0, jv = 0;
    if (active) {
        jlx = g_geo[b][0][j]; jly = g_geo[b][1][j]; jlz = g_geo[b][2][j];
        jhx = g_geo[b][3][j]; jhy = g_geo[b][4][j]; jhz = g_geo[b][5][j];
        jv  = g_geo[b][6][j];
    }

    __shared__ float s[7][128];
    for (int i0 = i_lo; i0 < i_hi; i0 += 128) {
        int ii = i0 + tid;
        if (ii < i_hi) {
            #pragma unroll
            for (int q = 0; q < 7; ++q) s[q][tid] = g_geo[b][q][ii];
        }
        __syncthreads();
        if (active) {
            int lim = min(128, i_hi - i0);
            for (int k = 0; k < lim; ++k) {
                int i = i0 + k;
                if (i >= j) break;
                float dxx = fminf(jhx, s[3][k]) - fmaxf(jlx, s[0][k]);
                if (dxx <= 0.f) continue;
                float dyy = fminf(jhy, s[4][k]) - fmaxf(jly, s[1][k]);
                if (dyy <= 0.f) continue;
                float dzz = fminf(jhz, s[5][k]) - fmaxf(jlz, s[2][k]);
                if (dzz <= 0.f) continue;
                float inter = dxx * dyy * dzz;
                float iou = inter / fmaxf(jv + s[6][k] - inter, 1e-8f);
                if (iou > NMS_TH) {
                    int p = atomicAdd(&g_pcnt[b], 1);
                    if (p < PCAP)
                        g_pairs[b][p] = ((unsigned)i << 16) | (unsigned)j;
                }
            }
        }
        __syncthreads();
    }
}

// ================= K8: serial greedy resolution over sparse conflicts =================
__global__ void __launch_bounds__(256) k_resolve() {
    const int b = blockIdx.x;
    const int tid = threadIdx.x;
    __shared__ unsigned pr[PCAP];
    __shared__ unsigned keepw[128];
    __shared__ int scan[126];

    int m = g_pcnt[b];
    if (m > PCAP) m = PCAP;
    int n2 = 32;
    while (n2 < m) n2 <<= 1;
    for (int i = tid; i < n2; i += 256) pr[i] = (i < m) ? g_pairs[b][i] : 0xFFFFFFFFu;
    __syncthreads();

    // bitonic sort ascending -> deterministic pair order (i asc, then j asc)
    for (int k = 2; k <= n2; k <<= 1) {
        for (int jj = k >> 1; jj > 0; jj >>= 1) {
            for (int t = tid; t < n2; t += 256) {
                int ixj = t ^ jj;
                if (ixj > t) {
                    unsigned a = pr[t], c2 = pr[ixj];
                    bool up = ((t & k) == 0);
                    if (up ? (a > c2) : (a < c2)) { pr[t] = c2; pr[ixj] = a; }
                }
            }
            __syncthreads();
        }
    }

    for (int t = tid; t < 128; t += 256) keepw[t] = 0xFFFFFFFFu;
    __syncthreads();

    // exact greedy: pairs sorted by i ascending; keep[i] is final before use
    if (tid == 0) {
        for (int p = 0; p < m; ++p) {
            unsigned u = pr[p];
            int i = (int)(u >> 16);
            int j = (int)(u & 0xFFFFu);
            if ((keepw[i >> 5] >> (i & 31)) & 1u)
                keepw[j >> 5] &= ~(1u << (j & 31));
        }
        // rank-order compaction offsets (125 words cover exactly PRE=4000 bits)
        int run = 0;
        for (int w = 0; w < 125; ++w) {
            scan[w] = run;
            run += __popc(keepw[w]);
        }
        scan[125] = run;
        g_nk[b] = run < POST ? run : POST;
    }
    __syncthreads();

    if (tid < 125) {
        unsigned w = keepw[tid];
        int base = scan[tid];
        while (w) {
            int l = __ffs(w) - 1;
            w &= w - 1;
            if (base < POST) g_order[b][base] = tid * 32 + l;
            ++base;
        }
    }
}

// ================= K9: output =================
__global__ void k_out(float* __restrict__ out) {
    const int stride = gridDim.x * blockDim.x;
    for (int t = blockIdx.x * blockDim.x + threadIdx.x; t < NB * POST; t += stride) {
        int b = t / POST;
        int r = t % POST;
        float row[8];
        if (r < g_nk[b]) {
            int rr = g_order[b][r];
            #pragma unroll
            for (int q = 0; q < 7; ++q) row[q] = g_box[b][rr][q];
            row[7] = g_score[b][rr];
        } else {
            #pragma unroll
            for (int q = 0; q < 8; ++q) row[q] = 0.f;
        }
        float4* o4 = (float4*)(out + (size_t)t * 8);
        o4[0] = make_float4(row[0], row[1], row[2], row[3]);
        o4[1] = make_float4(row[4], row[5], row[6], row[7]);
    }
}

extern "C" void kernel_launch(void* const* d_in, const int* in_sizes, int n_in,
                              void* d_out, int out_size) {
    const float* obj = (const float*)d_in[0];
    const float* reg = (const float*)d_in[1];
    const float* anc = (const float*)d_in[2];
    float* out = (float*)d_out;

    k_zero<<<256, 256>>>();
    k_hist_hi<<<NB * HCTA, HTHR>>>(obj);
    k_scan_hi<<<NB, NT>>>();
    k_hist_lo<<<NB * HCTA, HTHR>>>(obj);
    k_scan_lo<<<NB, NT>>>();
    k_compact<<<NB * HCTA, HTHR>>>(obj);
    k_rank<<<NB * RCTA, RTHR>>>(reg, anc);
    k_pairs<<<NB * JBLK * ICHK, 128>>>();
    k_resolve<<<NB, 256>>>();
    k_out<<<32, 128>>>(out);
}

// round 5
// speedup vs baseline: 4.7425x; 1.3743x over previous
#include <cuda_runtime.h>
#include <math.h>

#define NB 4
#define NA 262144
#define PRE 4000
#define POST 1000
#define NBIN 16384
#define BSHIFT 18
#define CAND 8192
#define HCTA 64          // hist CTAs per batch
#define HTHR 256
#define CCTA 128         // compact CTAs per batch
#define CTHR 256
#define RTHR 256
#define RCTA (CAND / RTHR)   // 32 rank CTAs per batch
#define PCAP 8192

static __device__ const float NMS_TH = 0.3f;
static __device__ const float AUG = 0.2f;

// ---- global scratch (zero-initialized; k_out re-zeroes what k_hist/compact/pairs dirty) ----
__device__ unsigned g_hist[NB][NBIN];
__device__ unsigned g_selbin[NB];
__device__ unsigned long long g_keys[NB][CAND];
__device__ int g_cnt[NB];
__device__ float g_geo[NB][7][PRE];
__device__ float g_box[NB][PRE][7];
__device__ float g_score[NB][PRE];
__device__ unsigned g_pairs[NB][PCAP];
__device__ int g_pcnt[NB];
__device__ int g_order[NB][POST];
__device__ int g_nk[NB];

__device__ __forceinline__ unsigned mapf(float v) {
    unsigned u = __float_as_uint(v);
    return (u & 0x80000000u) ? ~u : (u | 0x80000000u);
}
__device__ __forceinline__ float unmapf(unsigned m) {
    return __uint_as_float((m & 0x80000000u) ? (m & 0x7FFFFFFFu) : ~m);
}

__device__ __forceinline__ void decode_box(const float* __restrict__ rg,
                                           const float* __restrict__ an,
                                           float* bx) {
    float xa = an[0], ya = an[1], za = an[2];
    float wa = an[3], la = an[4], ha = an[5], ra = an[6];
    float diag = sqrtf(wa * wa + la * la);
    bx[0] = rg[0] * diag + xa;
    bx[1] = rg[1] * diag + ya;
    bx[2] = rg[2] * ha + za;
    bx[3] = expf(rg[3]) * wa;
    bx[4] = expf(rg[4]) * la;
    bx[5] = expf(rg[5]) * ha;
    bx[6] = rg[6] + ra;
}

// ================= K1: 14-bit smem histogram, sparse merge =================
__global__ void __launch_bounds__(HTHR) k_hist(const float* __restrict__ obj) {
    __shared__ unsigned sh[NBIN];
    const int b = blockIdx.x / HCTA;
    const int c = blockIdx.x % HCTA;
    const int tid = threadIdx.x;
    for (int i = tid; i < NBIN; i += HTHR) sh[i] = 0u;
    __syncthreads();
    const int CHUNK = NA / HCTA / 4;  // float4s per CTA
    const float4* o4 = (const float4*)(obj + (size_t)b * NA) + (size_t)c * CHUNK;
    for (int i = tid; i < CHUNK; i += HTHR) {
        float4 v = o4[i];
        atomicAdd(&sh[mapf(v.x) >> BSHIFT], 1u);
        atomicAdd(&sh[mapf(v.y) >> BSHIFT], 1u);
        atomicAdd(&sh[mapf(v.z) >> BSHIFT], 1u);
        atomicAdd(&sh[mapf(v.w) >> BSHIFT], 1u);
    }
    __syncthreads();
    for (int i = tid; i < NBIN; i += HTHR) {
        unsigned cnt = sh[i];
        if (cnt) atomicAdd(&g_hist[b][i], cnt);
    }
}

// ================= K2: select threshold bin per batch =================
__global__ void __launch_bounds__(256) k_selbin() {
    const int b = blockIdx.x;
    const int tid = threadIdx.x;
    __shared__ unsigned ssum[256];
    const unsigned* h = g_hist[b];
    const int CW = NBIN / 256;  // 64 bins per thread
    const int base = tid * CW;
    unsigned csum = 0;
    #pragma unroll
    for (int k = 0; k < CW; ++k) csum += h[base + k];
    unsigned orig = csum;
    ssum[tid] = csum;
    __syncthreads();
    // inclusive suffix sum
    for (int d = 1; d < 256; d <<= 1) {
        unsigned v = (tid + d < 256) ? ssum[tid + d] : 0u;
        __syncthreads();
        ssum[tid] += v;
        __syncthreads();
    }
    unsigned inc = ssum[tid];
    unsigned exc = inc - orig;
    if (exc < PRE && inc >= PRE) {
        unsigned run = exc;
        for (int k = CW - 1; k >= 0; --k) {
            run += h[base + k];
            if (run >= PRE) {
                g_selbin[b] = (unsigned)(base + k);
                break;
            }
        }
    }
}

// ================= K3: compact all candidates in bins >= selbin =================
__global__ void __launch_bounds__(CTHR) k_compact(const float* __restrict__ obj) {
    const int b = blockIdx.x / CCTA;
    const int c = blockIdx.x % CCTA;
    const unsigned sb = g_selbin[b];
    const unsigned T = sb << BSHIFT;  // u >= T  <=>  (u >> BSHIFT) >= sb
    const int lane = threadIdx.x & 31;
    const int CHUNK = NA / CCTA / 4;
    const float4* o4 = (const float4*)(obj + (size_t)b * NA) + (size_t)c * CHUNK;
    for (int i = threadIdx.x; i < CHUNK; i += CTHR) {
        float4 v = o4[i];
        unsigned uu[4] = {mapf(v.x), mapf(v.y), mapf(v.z), mapf(v.w)};
        int e0 = (c * CHUNK + i) * 4;
        #pragma unroll
        for (int q = 0; q < 4; ++q) {
            bool has = uu[q] >= T;
            unsigned mk = __ballot_sync(0xffffffffu, has);
            if (mk) {
                int ldr = __ffs(mk) - 1;
                int bpos = 0;
                if (lane == ldr) bpos = atomicAdd(&g_cnt[b], __popc(mk));
                bpos = __shfl_sync(0xffffffffu, bpos, ldr);
                int pos = bpos + __popc(mk & ((1u << lane) - 1u));
                if (has && pos < CAND)
                    g_keys[b][pos] =
                        ((unsigned long long)uu[q] << 32) | (unsigned)(~(e0 + q));
            }
        }
    }
}

// ================= K4: exact stable rank + decode + scatter =================
__global__ void __launch_bounds__(RTHR) k_rank(
    const float* __restrict__ reg, const float* __restrict__ anc)
{
    extern __shared__ unsigned long long sk[];   // CAND u64 = 64 KB
    const int b = blockIdx.x / RCTA;
    const int c = blockIdx.x % RCTA;
    int cc = g_cnt[b];
    if (cc > CAND) cc = CAND;
    if (c * RTHR >= cc) return;   // whole block idle

    for (int i = threadIdx.x; i < cc; i += RTHR) sk[i] = g_keys[b][i];
    __syncthreads();

    const int i = c * RTHR + threadIdx.x;
    if (i >= cc) return;
    const unsigned long long me = sk[i];
    int rank = 0;
    #pragma unroll 8
    for (int j = 0; j < cc; ++j) rank += (sk[j] > me);

    if (rank < PRE) {
        int idx = (int)(~(unsigned)(me & 0xFFFFFFFFull));
        const float* rg = reg + ((size_t)b * NA + idx) * 7;
        const float* an = anc + ((size_t)b * NA + idx) * 7;
        float bx[7];
        decode_box(rg, an, bx);
        #pragma unroll
        for (int q = 0; q < 7; ++q) g_box[b][rank][q] = bx[q];
        float lg = unmapf((unsigned)(me >> 32));
        g_score[b][rank] = 1.0f / (1.0f + expf(-lg));
        float sx = fmaxf(bx[3], AUG);
        float sy = fmaxf(bx[4], AUG);
        float sz = fmaxf(bx[5], AUG);
        g_geo[b][0][rank] = bx[0] - sx * 0.5f;
        g_geo[b][1][rank] = bx[1] - sy * 0.5f;
        g_geo[b][2][rank] = bx[2];
        g_geo[b][3][rank] = bx[0] + sx * 0.5f;
        g_geo[b][4][rank] = bx[1] + sy * 0.5f;
        g_geo[b][5][rank] = bx[2] + sz;
        g_geo[b][6][rank] = sx * sy * sz;
    }
}

// ================= K5: chip-wide conflict-pair discovery =================
#define JBLK 32
#define ICHK 4
__global__ void __launch_bounds__(128) k_pairs() {
    const int bx = blockIdx.x;
    const int ic = bx & (ICHK - 1);
    const int jb = (bx >> 2) & (JBLK - 1);
    const int b = bx >> 7;
    const int tid = threadIdx.x;

    const int j = jb * 128 + tid;
    const int jmax = min(PRE, jb * 128 + 128);
    const int i_lo = ic * 1024;
    const int i_hi = min(min((ic + 1) * 1024, PRE), jmax);
    if (i_lo >= i_hi) return;

    const bool active = (j < PRE);
    float jlx = 0, jly = 0, jlz = 0, jhx = 0, jhy = 0, jhz = 0, jv = 0;
    if (active) {
        jlx = g_geo[b][0][j]; jly = g_geo[b][1][j]; jlz = g_geo[b][2][j];
        jhx = g_geo[b][3][j]; jhy = g_geo[b][4][j]; jhz = g_geo[b][5][j];
        jv  = g_geo[b][6][j];
    }

    __shared__ float s[7][128];
    for (int i0 = i_lo; i0 < i_hi; i0 += 128) {
        int ii = i0 + tid;
        if (ii < i_hi) {
            #pragma unroll
            for (int q = 0; q < 7; ++q) s[q][tid] = g_geo[b][q][ii];
        }
        __syncthreads();
        if (active) {
            int lim = min(128, i_hi - i0);
            for (int k = 0; k < lim; ++k) {
                int i = i0 + k;
                if (i >= j) break;
                float dxx = fminf(jhx, s[3][k]) - fmaxf(jlx, s[0][k]);
                if (dxx <= 0.f) continue;
                float dyy = fminf(jhy, s[4][k]) - fmaxf(jly, s[1][k]);
                if (dyy <= 0.f) continue;
                float dzz = fminf(jhz, s[5][k]) - fmaxf(jlz, s[2][k]);
                if (dzz <= 0.f) continue;
                float inter = dxx * dyy * dzz;
                float iou = inter / fmaxf(jv + s[6][k] - inter, 1e-8f);
                if (iou > NMS_TH) {
                    int p = atomicAdd(&g_pcnt[b], 1);
                    if (p < PCAP)
                        g_pairs[b][p] = ((unsigned)i << 16) | (unsigned)j;
                }
            }
        }
        __syncthreads();
    }
}

// ================= K6: serial greedy resolution over sparse conflicts =================
__global__ void __launch_bounds__(256) k_resolve() {
    const int b = blockIdx.x;
    const int tid = threadIdx.x;
    __shared__ unsigned pr[PCAP];
    __shared__ unsigned keepw[128];
    __shared__ int scan[126];

    int m = g_pcnt[b];
    if (m > PCAP) m = PCAP;
    int n2 = 32;
    while (n2 < m) n2 <<= 1;
    for (int i = tid; i < n2; i += 256) pr[i] = (i < m) ? g_pairs[b][i] : 0xFFFFFFFFu;
    __syncthreads();

    for (int k = 2; k <= n2; k <<= 1) {
        for (int jj = k >> 1; jj > 0; jj >>= 1) {
            for (int t = tid; t < n2; t += 256) {
                int ixj = t ^ jj;
                if (ixj > t) {
                    unsigned a = pr[t], c2 = pr[ixj];
                    bool up = ((t & k) == 0);
                    if (up ? (a > c2) : (a < c2)) { pr[t] = c2; pr[ixj] = a; }
                }
            }
            __syncthreads();
        }
    }

    for (int t = tid; t < 128; t += 256) keepw[t] = 0xFFFFFFFFu;
    __syncthreads();

    if (tid == 0) {
        for (int p = 0; p < m; ++p) {
            unsigned u = pr[p];
            int i = (int)(u >> 16);
            int j = (int)(u & 0xFFFFu);
            if ((keepw[i >> 5] >> (i & 31)) & 1u)
                keepw[j >> 5] &= ~(1u << (j & 31));
        }
        int run = 0;
        for (int w = 0; w < 125; ++w) {
            scan[w] = run;
            run += __popc(keepw[w]);
        }
        g_nk[b] = run < POST ? run : POST;
    }
    __syncthreads();

    if (tid < 125) {
        unsigned w = keepw[tid];
        int base = scan[tid];
        while (w) {
            int l = __ffs(w) - 1;
            w &= w - 1;
            if (base < POST) g_order[b][base] = tid * 32 + l;
            ++base;
        }
    }
}

// ================= K7: output + re-zero scratch for next replay =================
__global__ void k_out(float* __restrict__ out) {
    const int gt = blockIdx.x * blockDim.x + threadIdx.x;
    const int stride = gridDim.x * blockDim.x;
    for (int t = gt; t < NB * POST; t += stride) {
        int b = t / POST;
        int r = t % POST;
        float row[8];
        if (r < g_nk[b]) {
            int rr = g_order[b][r];
            #pragma unroll
            for (int q = 0; q < 7; ++q) row[q] = g_box[b][rr][q];
            row[7] = g_score[b][rr];
        } else {
            #pragma unroll
            for (int q = 0; q < 8; ++q) row[q] = 0.f;
        }
        float4* o4 = (float4*)(out + (size_t)t * 8);
        o4[0] = make_float4(row[0], row[1], row[2], row[3]);
        o4[1] = make_float4(row[4], row[5], row[6], row[7]);
    }
    // re-zero dirty scratch (kernel_launch is deterministic: starts zeroed every call)
    unsigned* h = &g_hist[0][0];
    for (int i = gt; i < NB * NBIN; i += stride) h[i] = 0u;
    if (gt < NB) {
        g_cnt[gt] = 0;
        g_pcnt[gt] = 0;
    }
}

extern "C" void kernel_launch(void* const* d_in, const int* in_sizes, int n_in,
                              void* d_out, int out_size) {
    const float* obj = (const float*)d_in[0];
    const float* reg = (const float*)d_in[1];
    const float* anc = (const float*)d_in[2];
    float* out = (float*)d_out;

    cudaFuncSetAttribute(k_rank, cudaFuncAttributeMaxDynamicSharedMemorySize,
                         CAND * 8);

    k_hist<<<NB * HCTA, HTHR>>>(obj);
    k_selbin<<<NB, 256>>>();
    k_compact<<<NB * CCTA, CTHR>>>(obj);
    k_rank<<<NB * RCTA, RTHR, CAND * 8>>>(reg, anc);
    k_pairs<<<NB * JBLK * ICHK, 128>>>();
    k_resolve<<<NB, 256>>>();
    k_out<<<32, 128>>>(out);
}

// round 6
// speedup vs baseline: 4.9447x; 1.0426x over previous
#include <cuda_runtime.h>
#include <math.h>

#define NB 4
#define NA 262144
#define PRE 4000
#define POST 1000
#define NBIN 16384
#define BSHIFT 18
#define KCAP 12288
#define HCTA 64
#define HTHR 256
#define SCTA 128
#define STHR 256
#define RTHR 256
#define RCTA (KCAP / RTHR)    // 48 rank CTAs per batch
#define PCAP 8192

static __device__ const float NMS_TH = 0.3f;
static __device__ const float AUG = 0.2f;

// ---- global scratch (zero-init; k_final re-zeroes everything dirtied) ----
__device__ unsigned g_hist[NB][NBIN];
__device__ unsigned g_bincnt[NB][NBIN];
__device__ int g_base[NB][NBIN];
__device__ unsigned g_selbin[NB];
__device__ int g_cc[NB];
__device__ unsigned long long g_keys2[NB][KCAP];
__device__ float g_geo[NB][7][PRE];
__device__ float g_box[NB][PRE][7];
__device__ float g_score[NB][PRE];
__device__ unsigned g_pairs[NB][PCAP];
__device__ int g_pcnt[NB];

__device__ __forceinline__ unsigned mapf(float v) {
    unsigned u = __float_as_uint(v);
    return (u & 0x80000000u) ? ~u : (u | 0x80000000u);
}
__device__ __forceinline__ float unmapf(unsigned m) {
    return __uint_as_float((m & 0x80000000u) ? (m & 0x7FFFFFFFu) : ~m);
}

__device__ __forceinline__ void decode_box(const float* __restrict__ rg,
                                           const float* __restrict__ an,
                                           float* bx) {
    float xa = an[0], ya = an[1], za = an[2];
    float wa = an[3], la = an[4], ha = an[5], ra = an[6];
    float diag = sqrtf(wa * wa + la * la);
    bx[0] = rg[0] * diag + xa;
    bx[1] = rg[1] * diag + ya;
    bx[2] = rg[2] * ha + za;
    bx[3] = expf(rg[3]) * wa;
    bx[4] = expf(rg[4]) * la;
    bx[5] = expf(rg[5]) * ha;
    bx[6] = rg[6] + ra;
}

// ================= K1: 14-bit smem histogram =================
__global__ void __launch_bounds__(HTHR) k_hist(const float* __restrict__ obj) {
    __shared__ unsigned sh[NBIN];
    const int b = blockIdx.x / HCTA;
    const int c = blockIdx.x % HCTA;
    const int tid = threadIdx.x;
    for (int i = tid; i < NBIN; i += HTHR) sh[i] = 0u;
    __syncthreads();
    const int CHUNK = NA / HCTA / 4;
    const float4* o4 = (const float4*)(obj + (size_t)b * NA) + (size_t)c * CHUNK;
    for (int i = tid; i < CHUNK; i += HTHR) {
        float4 v = o4[i];
        atomicAdd(&sh[mapf(v.x) >> BSHIFT], 1u);
        atomicAdd(&sh[mapf(v.y) >> BSHIFT], 1u);
        atomicAdd(&sh[mapf(v.z) >> BSHIFT], 1u);
        atomicAdd(&sh[mapf(v.w) >> BSHIFT], 1u);
    }
    __syncthreads();
    for (int i = tid; i < NBIN; i += HTHR) {
        unsigned cnt = sh[i];
        if (cnt) atomicAdd(&g_hist[b][i], cnt);
    }
}

// ================= K2: suffix-sum base[] + selbin + cc =================
__global__ void __launch_bounds__(256) k_selbase() {
    const int b = blockIdx.x;
    const int tid = threadIdx.x;
    __shared__ unsigned ssum[256];
    const unsigned* h = g_hist[b];
    const int CW = NBIN / 256;
    const int bi = tid * CW;
    unsigned csum = 0;
    unsigned loc[CW > 0 ? CW : 1];
    #pragma unroll
    for (int k = 0; k < CW; ++k) {
        loc[k] = h[bi + k];
        csum += loc[k];
    }
    unsigned orig = csum;
    ssum[tid] = csum;
    __syncthreads();
    for (int d = 1; d < 256; d <<= 1) {
        unsigned v = (tid + d < 256) ? ssum[tid + d] : 0u;
        __syncthreads();
        ssum[tid] += v;
        __syncthreads();
    }
    // suffix-exclusive count above this chunk
    unsigned run = ssum[tid] - orig;
    for (int k = CW - 1; k >= 0; --k) {
        int bin = bi + k;
        g_base[b][bin] = (int)run;
        unsigned nb2 = run + loc[k];
        if (run < PRE && nb2 >= PRE) {
            g_selbin[b] = (unsigned)bin;
            g_cc[b] = (int)nb2;
        }
        run = nb2;
    }
}

// ================= K3: binned scatter of candidates =================
__global__ void __launch_bounds__(STHR) k_scatter(const float* __restrict__ obj) {
    const int b = blockIdx.x / SCTA;
    const int c = blockIdx.x % SCTA;
    const unsigned T = g_selbin[b] << BSHIFT;
    const int CHUNK = NA / SCTA / 4;
    const float4* o4 = (const float4*)(obj + (size_t)b * NA) + (size_t)c * CHUNK;
    for (int i = threadIdx.x; i < CHUNK; i += STHR) {
        float4 v = o4[i];
        unsigned uu[4] = {mapf(v.x), mapf(v.y), mapf(v.z), mapf(v.w)};
        int e0 = (c * CHUNK + i) * 4;
        #pragma unroll
        for (int q = 0; q < 4; ++q) {
            if (uu[q] >= T) {
                int bin = uu[q] >> BSHIFT;
                int slot = g_base[b][bin] + (int)atomicAdd(&g_bincnt[b][bin], 1u);
                if (slot < KCAP)
                    g_keys2[b][slot] =
                        ((unsigned long long)uu[q] << 32) | (unsigned)(~(e0 + q));
            }
        }
    }
}

// ================= K4: two-level exact rank + decode + scatter =================
__global__ void __launch_bounds__(RTHR) k_rank(
    const float* __restrict__ reg, const float* __restrict__ anc)
{
    const int b = blockIdx.x / RCTA;
    const int c = blockIdx.x % RCTA;
    int cc = g_cc[b];
    if (cc > KCAP) cc = KCAP;
    const int s = c * RTHR + threadIdx.x;
    if (s >= cc) return;

    const unsigned long long me = g_keys2[b][s];
    const unsigned u = (unsigned)(me >> 32);
    const int bin = (int)(u >> BSHIFT);
    const int lo = g_base[b][bin];
    int hi = lo + (int)g_hist[b][bin];
    if (hi > cc) hi = cc;
    int rank = lo;
    for (int t = lo; t < hi; ++t) rank += (g_keys2[b][t] > me);

    if (rank < PRE) {
        int idx = (int)(~(unsigned)(me & 0xFFFFFFFFull));
        const float* rg = reg + ((size_t)b * NA + idx) * 7;
        const float* an = anc + ((size_t)b * NA + idx) * 7;
        float bx[7];
        decode_box(rg, an, bx);
        #pragma unroll
        for (int q = 0; q < 7; ++q) g_box[b][rank][q] = bx[q];
        float lg = unmapf(u);
        g_score[b][rank] = 1.0f / (1.0f + expf(-lg));
        float sx = fmaxf(bx[3], AUG);
        float sy = fmaxf(bx[4], AUG);
        float sz = fmaxf(bx[5], AUG);
        g_geo[b][0][rank] = bx[0] - sx * 0.5f;
        g_geo[b][1][rank] = bx[1] - sy * 0.5f;
        g_geo[b][2][rank] = bx[2];
        g_geo[b][3][rank] = bx[0] + sx * 0.5f;
        g_geo[b][4][rank] = bx[1] + sy * 0.5f;
        g_geo[b][5][rank] = bx[2] + sz;
        g_geo[b][6][rank] = sx * sy * sz;
    }
}

// ================= K5: chip-wide conflict-pair discovery =================
#define JBLK 32
#define ICHK 4
__global__ void __launch_bounds__(128) k_pairs() {
    const int bx = blockIdx.x;
    const int ic = bx & (ICHK - 1);
    const int jb = (bx >> 2) & (JBLK - 1);
    const int b = bx >> 7;
    const int tid = threadIdx.x;

    const int j = jb * 128 + tid;
    const int jmax = min(PRE, jb * 128 + 128);
    const int i_lo = ic * 1024;
    const int i_hi = min(min((ic + 1) * 1024, PRE), jmax);
    if (i_lo >= i_hi) return;

    const bool active = (j < PRE);
    float jlx = 0, jly = 0, jlz = 0, jhx = 0, jhy = 0, jhz = 0, jv = 0;
    if (active) {
        jlx = g_geo[b][0][j]; jly = g_geo[b][1][j]; jlz = g_geo[b][2][j];
        jhx = g_geo[b][3][j]; jhy = g_geo[b][4][j]; jhz = g_geo[b][5][j];
        jv  = g_geo[b][6][j];
    }

    __shared__ float s[7][128];
    for (int i0 = i_lo; i0 < i_hi; i0 += 128) {
        int ii = i0 + tid;
        if (ii < i_hi) {
            #pragma unroll
            for (int q = 0; q < 7; ++q) s[q][tid] = g_geo[b][q][ii];
        }
        __syncthreads();
        if (active) {
            int lim = min(128, i_hi - i0);
            for (int k = 0; k < lim; ++k) {
                int i = i0 + k;
                if (i >= j) break;
                float dxx = fminf(jhx, s[3][k]) - fmaxf(jlx, s[0][k]);
                if (dxx <= 0.f) continue;
                float dyy = fminf(jhy, s[4][k]) - fmaxf(jly, s[1][k]);
                if (dyy <= 0.f) continue;
                float dzz = fminf(jhz, s[5][k]) - fmaxf(jlz, s[2][k]);
                if (dzz <= 0.f) continue;
                float inter = dxx * dyy * dzz;
                float iou = inter / fmaxf(jv + s[6][k] - inter, 1e-8f);
                if (iou > NMS_TH) {
                    int p = atomicAdd(&g_pcnt[b], 1);
                    if (p < PCAP)
                        g_pairs[b][p] = ((unsigned)i << 16) | (unsigned)j;
                }
            }
        }
        __syncthreads();
    }
}

// ================= K6: resolve + output + re-zero scratch =================
__global__ void __launch_bounds__(256) k_final(float* __restrict__ out) {
    const int b = blockIdx.x;
    const int tid = threadIdx.x;
    __shared__ unsigned pr[PCAP];
    __shared__ unsigned keepw[128];
    __shared__ int scan[126];
    __shared__ int order[POST];
    __shared__ int s_nk;

    int m = g_pcnt[b];
    if (m > PCAP) m = PCAP;
    int n2 = 32;
    while (n2 < m) n2 <<= 1;
    for (int i = tid; i < n2; i += 256) pr[i] = (i < m) ? g_pairs[b][i] : 0xFFFFFFFFu;
    __syncthreads();

    // bitonic sort ascending -> deterministic (i asc, then j asc)
    for (int k = 2; k <= n2; k <<= 1) {
        for (int jj = k >> 1; jj > 0; jj >>= 1) {
            for (int t = tid; t < n2; t += 256) {
                int ixj = t ^ jj;
                if (ixj > t) {
                    unsigned a = pr[t], c2 = pr[ixj];
                    bool up = ((t & k) == 0);
                    if (up ? (a > c2) : (a < c2)) { pr[t] = c2; pr[ixj] = a; }
                }
            }
            __syncthreads();
        }
    }

    for (int t = tid; t < 128; t += 256) keepw[t] = 0xFFFFFFFFu;
    __syncthreads();

    // exact greedy over sorted conflict pairs
    if (tid == 0) {
        for (int p = 0; p < m; ++p) {
            unsigned u = pr[p];
            int i = (int)(u >> 16);
            int j = (int)(u & 0xFFFFu);
            if ((keepw[i >> 5] >> (i & 31)) & 1u)
                keepw[j >> 5] &= ~(1u << (j & 31));
        }
        int run = 0;
        for (int w = 0; w < 125; ++w) {
            scan[w] = run;
            run += __popc(keepw[w]);
        }
        s_nk = run < POST ? run : POST;
    }
    __syncthreads();

    if (tid < 125) {
        unsigned w = keepw[tid];
        int base = scan[tid];
        while (w && base < POST) {
            int l = __ffs(w) - 1;
            w &= w - 1;
            order[base] = tid * 32 + l;
            ++base;
        }
    }
    __syncthreads();

    // output
    const int nk = s_nk;
    float* outb = out + (size_t)b * POST * 8;
    for (int r = tid; r < POST; r += 256) {
        float row[8];
        if (r < nk) {
            int rr = order[r];
            #pragma unroll
            for (int q = 0; q < 7; ++q) row[q] = g_box[b][rr][q];
            row[7] = g_score[b][rr];
        } else {
            #pragma unroll
            for (int q = 0; q < 8; ++q) row[q] = 0.f;
        }
        float4* o4 = (float4*)(outb + (size_t)r * 8);
        o4[0] = make_float4(row[0], row[1], row[2], row[3]);
        o4[1] = make_float4(row[4], row[5], row[6], row[7]);
    }

    // re-zero this batch's scratch for the next replay
    for (int i = tid; i < NBIN; i += 256) {
        g_hist[b][i] = 0u;
        g_bincnt[b][i] = 0u;
    }
    if (tid == 0) g_pcnt[b] = 0;
}

extern "C" void kernel_launch(void* const* d_in, const int* in_sizes, int n_in,
                              void* d_out, int out_size) {
    const float* obj = (const float*)d_in[0];
    const float* reg = (const float*)d_in[1];
    const float* anc = (const float*)d_in[2];
    float* out = (float*)d_out;

    k_hist<<<NB * HCTA, HTHR>>>(obj);
    k_selbase<<<NB, 256>>>();
    k_scatter<<<NB * SCTA, STHR>>>(obj);
    k_rank<<<NB * RCTA, RTHR>>>(reg, anc);
    k_pairs<<<NB * JBLK * ICHK, 128>>>();
    k_final<<<NB, 256>>>(out);
}